// round 4
// baseline (speedup 1.0000x reference)
#include <cuda_runtime.h>

#define N_IN  1024
#define N_OUT 512
#define BATCH 128
#define M     (N_IN + 1)    // 1025 word lines (weights + bias row)
#define TJ    8             // j-columns per block
#define NCH   32            // i-chunks
#define NJT   (N_OUT / TJ)  // 64 j-tiles
#define NI_MAX 33           // max rows per chunk (1025 = 32*32 + 1)

// ---- device scratch (no allocations allowed) ----
__device__ unsigned g_maxbits;        // bitwise max of |weights| (monotone, idempotent across replays)
__device__ float2   g_LS[M * BATCH];  // {lr, sign} transposed [i][b]

__device__ __forceinline__ float ex2f_(float x) {
    float r; asm("ex2.approx.ftz.f32 %0, %1;" : "=f"(r) : "f"(x)); return r;
}
__device__ __forceinline__ float lg2f_(float x) {
    float r; asm("lg2.approx.ftz.f32 %0, %1;" : "=f"(r) : "f"(x)); return r;
}

// K0: (a) float4 max|w| scan (bias 0.5 seeded; atomicMax on non-negative float bits is exact);
// (b) zero d_out (it is poisoned; k_main accumulates into it atomically);
// (c) LS = {1+log2|x|, sign(x)} transposed to [i][b] via 32x32 smem tiles (coalesced both ways).
__global__ void __launch_bounds__(256) k_prep(const float* __restrict__ wp,
                                              const float* __restrict__ wn,
                                              const float* __restrict__ x,
                                              float* __restrict__ out) {
    __shared__ float2 sm[32][33];
    const int tid    = threadIdx.x;
    const int gtid   = blockIdx.x * 256 + tid;
    const int stride = gridDim.x * 256;

    // (a) max over wp, wn — vectorized
    {
        const float4* wp4 = reinterpret_cast<const float4*>(wp);
        const float4* wn4 = reinterpret_cast<const float4*>(wn);
        float mx = 0.5f;
        for (int i = gtid; i < (N_IN * N_OUT) / 4; i += stride) {
            float4 a = wp4[i], c = wn4[i];
            mx = fmaxf(mx, fmaxf(fmaxf(fabsf(a.x), fabsf(a.y)), fmaxf(fabsf(a.z), fabsf(a.w))));
            mx = fmaxf(mx, fmaxf(fmaxf(fabsf(c.x), fabsf(c.y)), fmaxf(fabsf(c.z), fabsf(c.w))));
        }
        #pragma unroll
        for (int o = 16; o; o >>= 1)
            mx = fmaxf(mx, __shfl_xor_sync(0xFFFFFFFFu, mx, o));
        if ((tid & 31) == 0)
            atomicMax(&g_maxbits, __float_as_uint(mx));
    }

    // (b) zero the output
    {
        float4* out4 = reinterpret_cast<float4*>(out);
        for (int i = gtid; i < (BATCH * N_OUT) / 4; i += stride)
            out4[i] = make_float4(0.f, 0.f, 0.f, 0.f);
    }

    // (c) LS transpose: blocks 0..127 each handle a 32i x 32b tile of x
    if (blockIdx.x < 128) {
        const int it = blockIdx.x >> 2;          // 0..31  (i-tile)
        const int bt = blockIdx.x & 3;           // 0..3   (b-tile)
        const int i0 = it * 32, b0 = bt * 32;
        const int tx = tid & 31, tz = tid >> 5;  // tz = 0..7

        #pragma unroll
        for (int r = 0; r < 4; ++r) {            // read coalesced over i
            int bl = tz + r * 8;
            float xv = x[(b0 + bl) * N_IN + i0 + tx];
            float lr = lg2f_(fabsf(xv)) + 1.0f;  // log2(2|x|)
            float s  = (xv > 0.0f) ? 1.0f : ((xv < 0.0f) ? -1.0f : 0.0f);
            sm[bl][tx] = make_float2(lr, s);
        }
        __syncthreads();
        #pragma unroll
        for (int r = 0; r < 4; ++r) {            // write coalesced over b
            int il = tz + r * 8;
            g_LS[(i0 + il) * BATCH + b0 + tx] = sm[tx][il];
        }
    } else if (blockIdx.x == 128 && tid < BATCH) {
        // bias word line: x == 1 -> lr = log2(2) = 1, s = 1
        g_LS[N_IN * BATCH + tid] = make_float2(1.0f, 1.0f);
    }
}

// K1: main. Block = 128 threads (all b), TJ=8 columns, NCH=32 i-chunks.
// Params computed in the smem fill (each (i,j) visited by exactly one block):
//   Cp = 0.5*(wp + 0.25*maxw), Cn = -0.5*(wn + 0.25*maxw), E = log2(2.8 + 0.2*z)
// Epilogue: 8 float atomic adds per thread into out (zeroed by k_prep).
__global__ void __launch_bounds__(128, 12) k_main(const float* __restrict__ wp,
                                                  const float* __restrict__ wn,
                                                  const float* __restrict__ bp,
                                                  const float* __restrict__ bn,
                                                  const float* __restrict__ noise,
                                                  float* __restrict__ out) {
    __shared__ float4 sP[NI_MAX * TJ];           // 33*8*16B = 4.2 KB

    const int jt = blockIdx.x;                   // 0..63
    const int ch = blockIdx.y;                   // 0..31
    const int j0 = jt * TJ;
    const int i0 = (ch * M) / NCH;
    const int i1 = ((ch + 1) * M) / NCH;
    const int ni = i1 - i0;
    const int b  = threadIdx.x;

    const float off = 0.25f * __uint_as_float(g_maxbits);

    for (int t = b; t < ni * TJ; t += 128) {
        int ii = t >> 3, jj = t & (TJ - 1);
        int i = i0 + ii, j = j0 + jj;
        float wpv = (i < N_IN) ? wp[i * N_OUT + j] : bp[j];
        float wnv = (i < N_IN) ? wn[i * N_OUT + j] : bn[j];
        float2 z = reinterpret_cast<const float2*>(noise)[i * N_OUT + j]; // cols (2j,2j+1) of row i
        float4 P;
        P.x =  0.5f * (wpv + off);
        P.y = -0.5f * (wnv + off);
        P.z = lg2f_(2.8f + 0.2f * z.x);
        P.w = lg2f_(2.8f + 0.2f * z.y);
        sP[t] = P;
    }
    __syncthreads();

    float acc[TJ];
    #pragma unroll
    for (int jj = 0; jj < TJ; ++jj) acc[jj] = 0.0f;

    const float2* __restrict__ ls = &g_LS[i0 * BATCH + b];
    float2 l = ls[0];
    #pragma unroll 2
    for (int ii = 0; ii < ni; ++ii) {
        float2 lnext = (ii + 1 < ni) ? ls[(ii + 1) * BATCH] : l;  // prefetch next (i,b)
        #pragma unroll
        for (int jj = 0; jj < TJ; ++jj) {
            float4 p = sP[ii * TJ + jj];          // smem broadcast
            float pp = ex2f_(p.z * l.x);          // ratio^Ep
            float qq = ex2f_(p.w * l.x);          // ratio^En
            acc[jj] = fmaf(l.y, fmaf(p.x, pp, p.y * qq), acc[jj]);
        }
        l = lnext;
    }

    #pragma unroll
    for (int jj = 0; jj < TJ; ++jj)
        atomicAdd(&out[b * N_OUT + j0 + jj], acc[jj]);   // RED.F32, spread addresses
}

extern "C" void kernel_launch(void* const* d_in, const int* in_sizes, int n_in,
                              void* d_out, int out_size) {
    const float* x     = (const float*)d_in[0];   // (128, 1024)
    const float* w_pos = (const float*)d_in[1];   // (1024, 512)
    const float* w_neg = (const float*)d_in[2];   // (1024, 512)
    const float* b_pos = (const float*)d_in[3];   // (512,)
    const float* b_neg = (const float*)d_in[4];   // (512,)
    const float* noise = (const float*)d_in[5];   // (1025, 1024)
    float* out = (float*)d_out;                   // (128, 512)

    k_prep<<<592, 256>>>(w_pos, w_neg, x, out);
    dim3 grid(NJT, NCH);
    k_main<<<grid, 128>>>(w_pos, w_neg, b_pos, b_neg, noise, out);
}

// round 5
// speedup vs baseline: 1.0548x; 1.0548x over previous
#include <cuda_runtime.h>

#define N_IN  1024
#define N_OUT 512
#define BATCH 128
#define M     (N_IN + 1)    // 1025 word lines (weights + bias row)
#define TJ    16            // j-columns per block
#define NCH   32            // i-chunks
#define NJT   (N_OUT / TJ)  // 32 j-tiles -> grid 32*32 = 1024 blocks = one wave
#define NI_MAX 33           // max rows per chunk

// ---- device scratch (no allocations allowed) ----
__device__ unsigned g_maxbits;        // bitwise max of |weights| (monotone, idempotent across replays)
__device__ float2   g_LS[M * BATCH];  // {lr, sign} transposed [i][b]

__device__ __forceinline__ float ex2f_(float x) {
    float r; asm("ex2.approx.ftz.f32 %0, %1;" : "=f"(r) : "f"(x)); return r;
}
__device__ __forceinline__ float lg2f_(float x) {
    float r; asm("lg2.approx.ftz.f32 %0, %1;" : "=f"(r) : "f"(x)); return r;
}

// K0: (a) float4 max|w| scan (bias 0.5 seeded; atomicMax on non-negative float bits is exact);
// (b) zero d_out (poisoned; k_main accumulates atomically);
// (c) LS = {1+log2|x|, sign(x)} transposed to [i][b] via 32x32 smem tiles (coalesced both ways).
__global__ void __launch_bounds__(256) k_prep(const float* __restrict__ wp,
                                              const float* __restrict__ wn,
                                              const float* __restrict__ x,
                                              float* __restrict__ out) {
    __shared__ float2 sm[32][33];
    const int tid    = threadIdx.x;
    const int gtid   = blockIdx.x * 256 + tid;
    const int stride = gridDim.x * 256;

    // (a) max over wp, wn — vectorized
    {
        const float4* wp4 = reinterpret_cast<const float4*>(wp);
        const float4* wn4 = reinterpret_cast<const float4*>(wn);
        float mx = 0.5f;
        for (int i = gtid; i < (N_IN * N_OUT) / 4; i += stride) {
            float4 a = wp4[i], c = wn4[i];
            mx = fmaxf(mx, fmaxf(fmaxf(fabsf(a.x), fabsf(a.y)), fmaxf(fabsf(a.z), fabsf(a.w))));
            mx = fmaxf(mx, fmaxf(fmaxf(fabsf(c.x), fabsf(c.y)), fmaxf(fabsf(c.z), fabsf(c.w))));
        }
        #pragma unroll
        for (int o = 16; o; o >>= 1)
            mx = fmaxf(mx, __shfl_xor_sync(0xFFFFFFFFu, mx, o));
        if ((tid & 31) == 0)
            atomicMax(&g_maxbits, __float_as_uint(mx));
    }

    // (b) zero the output
    {
        float4* out4 = reinterpret_cast<float4*>(out);
        for (int i = gtid; i < (BATCH * N_OUT) / 4; i += stride)
            out4[i] = make_float4(0.f, 0.f, 0.f, 0.f);
    }

    // (c) LS transpose: blocks 0..127 each handle a 32i x 32b tile of x
    if (blockIdx.x < 128) {
        const int it = blockIdx.x >> 2;          // 0..31  (i-tile)
        const int bt = blockIdx.x & 3;           // 0..3   (b-tile)
        const int i0 = it * 32, b0 = bt * 32;
        const int tx = tid & 31, tz = tid >> 5;  // tz = 0..7

        #pragma unroll
        for (int r = 0; r < 4; ++r) {            // read coalesced over i
            int bl = tz + r * 8;
            float xv = x[(b0 + bl) * N_IN + i0 + tx];
            float lr = lg2f_(fabsf(xv)) + 1.0f;  // log2(2|x|); -inf at 0 -> ex2 -> 0, s==0 kills term
            float s  = (xv > 0.0f) ? 1.0f : ((xv < 0.0f) ? -1.0f : 0.0f);
            sm[bl][tx] = make_float2(lr, s);
        }
        __syncthreads();
        #pragma unroll
        for (int r = 0; r < 4; ++r) {            // write coalesced over b
            int il = tz + r * 8;
            g_LS[(i0 + il) * BATCH + b0 + tx] = sm[tx][il];
        }
    } else if (blockIdx.x == 128 && tid < BATCH) {
        // bias word line: x == 1 -> lr = log2(2) = 1, s = 1
        g_LS[N_IN * BATCH + tid] = make_float2(1.0f, 1.0f);
    }
}

// K1: main. Block = 128 threads (all b), TJ=16 columns, NCH=32 i-chunks (1024 blocks total).
// One i-iteration = 32 EX2 = 256 MUFU-cycles > L2 latency, so the single-iter ls prefetch
// fully hides the load. Params computed during the smem fill:
//   Cp = 0.5*(wp + 0.25*maxw), Cn = -0.5*(wn + 0.25*maxw), E = log2(2.8 + 0.2*z)
__global__ void __launch_bounds__(128, 8) k_main(const float* __restrict__ wp,
                                                 const float* __restrict__ wn,
                                                 const float* __restrict__ bp,
                                                 const float* __restrict__ bn,
                                                 const float* __restrict__ noise,
                                                 float* __restrict__ out) {
    __shared__ float4 sP[NI_MAX * TJ];           // 33*16*16B = 8.4 KB

    const int jt = blockIdx.x;                   // 0..31
    const int ch = blockIdx.y;                   // 0..31
    const int j0 = jt * TJ;
    const int i0 = (ch * M) / NCH;
    const int i1 = ((ch + 1) * M) / NCH;
    const int ni = i1 - i0;
    const int b  = threadIdx.x;

    const float off = 0.25f * __uint_as_float(g_maxbits);

    for (int t = b; t < ni * TJ; t += 128) {
        int ii = t >> 4, jj = t & (TJ - 1);
        int i = i0 + ii, j = j0 + jj;
        float wpv = (i < N_IN) ? wp[i * N_OUT + j] : bp[j];
        float wnv = (i < N_IN) ? wn[i * N_OUT + j] : bn[j];
        float2 z = reinterpret_cast<const float2*>(noise)[i * N_OUT + j]; // cols (2j,2j+1) of row i
        float4 P;
        P.x =  0.5f * (wpv + off);
        P.y = -0.5f * (wnv + off);
        P.z = lg2f_(2.8f + 0.2f * z.x);
        P.w = lg2f_(2.8f + 0.2f * z.y);
        sP[t] = P;
    }
    __syncthreads();

    float acc[TJ];
    #pragma unroll
    for (int jj = 0; jj < TJ; ++jj) acc[jj] = 0.0f;

    const float2* __restrict__ ls = &g_LS[i0 * BATCH + b];
    float2 l = ls[0];
    for (int ii = 0; ii < ni; ++ii) {
        float2 lnext = (ii + 1 < ni) ? ls[(ii + 1) * BATCH] : l;  // prefetch next (i,b)
        #pragma unroll
        for (int jj = 0; jj < TJ; ++jj) {
            float4 p = sP[ii * TJ + jj];          // smem broadcast
            float pp = ex2f_(p.z * l.x);          // ratio^Ep
            float qq = ex2f_(p.w * l.x);          // ratio^En
            acc[jj] = fmaf(l.y, fmaf(p.x, pp, p.y * qq), acc[jj]);
        }
        l = lnext;
    }

    #pragma unroll
    for (int jj = 0; jj < TJ; ++jj)
        atomicAdd(&out[b * N_OUT + j0 + jj], acc[jj]);   // RED.F32, spread addresses
}

extern "C" void kernel_launch(void* const* d_in, const int* in_sizes, int n_in,
                              void* d_out, int out_size) {
    const float* x     = (const float*)d_in[0];   // (128, 1024)
    const float* w_pos = (const float*)d_in[1];   // (1024, 512)
    const float* w_neg = (const float*)d_in[2];   // (1024, 512)
    const float* b_pos = (const float*)d_in[3];   // (512,)
    const float* b_neg = (const float*)d_in[4];   // (512,)
    const float* noise = (const float*)d_in[5];   // (1025, 1024)
    float* out = (float*)d_out;                   // (128, 512)

    k_prep<<<592, 256>>>(w_pos, w_neg, x, out);
    dim3 grid(NJT, NCH);
    k_main<<<grid, 128>>>(w_pos, w_neg, b_pos, b_neg, noise, out);
}